// round 2
// baseline (speedup 1.0000x reference)
#include <cuda_runtime.h>
#include <cstdint>

// Problem constants (fixed shapes for this problem instance)
#define B_DIM 8
#define N_NODES 100000
#define N_EDGES 3200000

// Scratch (allocation-free: __device__ globals)
__device__ float g_deg[N_NODES];          // 400 KB
__device__ float g_yT[N_NODES * B_DIM];   // 3.2 MB, [N][8] layout
__device__ float g_acc[N_NODES * B_DIM];  // 3.2 MB, [N][8] layout

// ---------------------------------------------------------------------------
// Kernel 1: zero deg + acc, transpose y [B,N] -> yT [N,8]
// ---------------------------------------------------------------------------
__global__ void init_kernel(const float* __restrict__ y) {
    int n = blockIdx.x * blockDim.x + threadIdx.x;
    if (n >= N_NODES) return;
    g_deg[n] = 0.0f;
    float4 z = make_float4(0.f, 0.f, 0.f, 0.f);
    float4* acc4 = reinterpret_cast<float4*>(g_acc);
    acc4[2 * n]     = z;
    acc4[2 * n + 1] = z;
    float v0 = y[0 * N_NODES + n];
    float v1 = y[1 * N_NODES + n];
    float v2 = y[2 * N_NODES + n];
    float v3 = y[3 * N_NODES + n];
    float v4 = y[4 * N_NODES + n];
    float v5 = y[5 * N_NODES + n];
    float v6 = y[6 * N_NODES + n];
    float v7 = y[7 * N_NODES + n];
    float4* yT4 = reinterpret_cast<float4*>(g_yT);
    yT4[2 * n]     = make_float4(v0, v1, v2, v3);
    yT4[2 * n + 1] = make_float4(v4, v5, v6, v7);
}

// ---------------------------------------------------------------------------
// Kernel 2: deg[n] = segment_sum(attr over ei0)
// edge_index arrives as int32 (harness downcasts int64)
// ---------------------------------------------------------------------------
__global__ void deg_kernel(const int* __restrict__ edge_index,
                           const float* __restrict__ attr) {
    int e = blockIdx.x * blockDim.x + threadIdx.x;
    if (e >= N_EDGES) return;
    int n0 = edge_index[e];  // ei0
    atomicAdd(&g_deg[n0], attr[e]);
}

// ---------------------------------------------------------------------------
// Kernel 3: per-edge contribution, vector reduction into acc [N][8]
// contribution[b] = sqrt(sigmoid(dw)) / deg[n0]^2 * max(y[b,n0]-y[b,n1], 0)
// ---------------------------------------------------------------------------
__device__ __forceinline__ void red_v4(float* addr, float4 v) {
    asm volatile("red.global.add.v4.f32 [%0], {%1, %2, %3, %4};"
                 :: "l"(addr), "f"(v.x), "f"(v.y), "f"(v.z), "f"(v.w)
                 : "memory");
}

__global__ void edge_kernel(const int* __restrict__ edge_index,
                            const float* __restrict__ dist_w) {
    int e = blockIdx.x * blockDim.x + threadIdx.x;
    if (e >= N_EDGES) return;

    int n0 = edge_index[e];             // ei0 (scatter target + gather)
    int n1 = edge_index[N_EDGES + e];   // ei1

    float d  = g_deg[n0];
    // sqrt(sigmoid(x)) = rsqrt(1 + exp(-x)); divide by deg^2
    float w  = rsqrtf(1.0f + __expf(-dist_w[e]));
    float inv = w / (d * d);

    const float4* yT4 = reinterpret_cast<const float4*>(g_yT);
    float4 a0 = yT4[2 * n0];
    float4 a1 = yT4[2 * n0 + 1];
    float4 b0 = yT4[2 * n1];
    float4 b1 = yT4[2 * n1 + 1];

    float4 c0, c1;
    c0.x = fmaxf(a0.x - b0.x, 0.0f) * inv;
    c0.y = fmaxf(a0.y - b0.y, 0.0f) * inv;
    c0.z = fmaxf(a0.z - b0.z, 0.0f) * inv;
    c0.w = fmaxf(a0.w - b0.w, 0.0f) * inv;
    c1.x = fmaxf(a1.x - b1.x, 0.0f) * inv;
    c1.y = fmaxf(a1.y - b1.y, 0.0f) * inv;
    c1.z = fmaxf(a1.z - b1.z, 0.0f) * inv;
    c1.w = fmaxf(a1.w - b1.w, 0.0f) * inv;

    float* base = g_acc + (size_t)n0 * 8;
    if (c0.x != 0.f || c0.y != 0.f || c0.z != 0.f || c0.w != 0.f)
        red_v4(base, c0);
    if (c1.x != 0.f || c1.y != 0.f || c1.z != 0.f || c1.w != 0.f)
        red_v4(base + 4, c1);
}

// ---------------------------------------------------------------------------
// Kernel 4: out[b,n] = 1 - acc[n,b]
// ---------------------------------------------------------------------------
__global__ void out_kernel(float* __restrict__ out) {
    int n = blockIdx.x * blockDim.x + threadIdx.x;
    if (n >= N_NODES) return;
    const float4* acc4 = reinterpret_cast<const float4*>(g_acc);
    float4 a = acc4[2 * n];
    float4 b = acc4[2 * n + 1];
    out[0 * N_NODES + n] = 1.0f - a.x;
    out[1 * N_NODES + n] = 1.0f - a.y;
    out[2 * N_NODES + n] = 1.0f - a.z;
    out[3 * N_NODES + n] = 1.0f - a.w;
    out[4 * N_NODES + n] = 1.0f - b.x;
    out[5 * N_NODES + n] = 1.0f - b.y;
    out[6 * N_NODES + n] = 1.0f - b.z;
    out[7 * N_NODES + n] = 1.0f - b.w;
}

// ---------------------------------------------------------------------------
// Launch: inputs are [y, t, graph_edge_attr, dist_w, edge_index]
// ---------------------------------------------------------------------------
extern "C" void kernel_launch(void* const* d_in, const int* in_sizes, int n_in,
                              void* d_out, int out_size) {
    const float* y    = (const float*)d_in[0];
    // d_in[1] = t (unused)
    const float* attr = (const float*)d_in[2];
    const float* dw   = (const float*)d_in[3];
    const int*   ei   = (const int*)d_in[4];
    float* out = (float*)d_out;

    const int TB = 256;
    init_kernel<<<(N_NODES + TB - 1) / TB, TB>>>(y);
    deg_kernel<<<(N_EDGES + TB - 1) / TB, TB>>>(ei, attr);
    edge_kernel<<<(N_EDGES + TB - 1) / TB, TB>>>(ei, dw);
    out_kernel<<<(N_NODES + TB - 1) / TB, TB>>>(out);
}